// round 6
// baseline (speedup 1.0000x reference)
#include <cuda_runtime.h>
#include <cuda_bf16.h>
#include <math.h>
#include <cstdint>

#define NN      16384
#define EE      262144
#define HID     128
#define NGAUSS  50
#define NINTER  6
#define NTAB    4096
#define DMAX    8.6610f
#define DELTA   (DMAX / (float)(NTAB - 1))
#define GSPACE  (10.0f / 49.0f)
#define GCOEFF  (-0.5f / (GSPACE * GSPACE))
#define LOG2F_C 0.69314718055994530942f
#define PI_O10  0.31415926535897932f

// ---------------- device scratch ----------------
__device__ float g_d[EE];
__device__ int   g_perm[EE];     // packed (t0 << 16) | src
__device__ float g_pw[EE];       // lerp weight
__device__ int   g_start[NN + 1];
__device__ int   g_cnt[NN];
__device__ float g_h[NN * HID];
__device__ __nv_bfloat16 g_xb[NN * HID];
__device__ float g_agg[NN * HID];
__device__ float g_H[NINTER * NTAB * HID];
__device__ __nv_bfloat16 g_Tb[NINTER * NTAB * HID];
__device__ float g_C[NTAB];
__device__ float g_sum;

__device__ __forceinline__ float sspf(float x) {
    float sp = (x > 15.0f) ? x : log1pf(expf(x));
    return sp - LOG2F_C;
}

// ---------------- prep kernels ----------------
__global__ void zero_kernel() {
    int i = blockIdx.x * blockDim.x + threadIdx.x;
    if (i < NN) g_cnt[i] = 0;
    if (i == 0) g_sum = 0.0f;
}

__global__ void prep_kernel(const float* __restrict__ pos, const int* __restrict__ ei) {
    int e = blockIdx.x * blockDim.x + threadIdx.x;
    if (e >= EE) return;
    int s = ei[e];
    int t = ei[EE + e];
    float dx = pos[3 * s + 0] - pos[3 * t + 0];
    float dy = pos[3 * s + 1] - pos[3 * t + 1];
    float dz = pos[3 * s + 2] - pos[3 * t + 2];
    g_d[e] = sqrtf(dx * dx + dy * dy + dz * dz);
    atomicAdd(&g_cnt[t], 1);
}

__global__ void scan_kernel() {
    __shared__ int part[1024];
    int tid = threadIdx.x;
    int base = tid * 16;
    int loc[16];
    int s = 0;
#pragma unroll
    for (int i = 0; i < 16; i++) { loc[i] = g_cnt[base + i]; s += loc[i]; }
    part[tid] = s;
    __syncthreads();
    for (int off = 1; off < 1024; off <<= 1) {
        int v = part[tid];
        int add = (tid >= off) ? part[tid - off] : 0;
        __syncthreads();
        part[tid] = v + add;
        __syncthreads();
    }
    int excl = (tid == 0) ? 0 : part[tid - 1];
#pragma unroll
    for (int i = 0; i < 16; i++) {
        g_start[base + i] = excl;
        g_cnt[base + i] = excl;
        excl += loc[i];
    }
    if (tid == 1023) g_start[NN] = excl;
}

__global__ void scatter_kernel(const int* __restrict__ ei) {
    int e = blockIdx.x * blockDim.x + threadIdx.x;
    if (e >= EE) return;
    int t = ei[EE + e];
    int s = ei[e];
    float dd = g_d[e];
    float f = dd * (1.0f / DELTA);
    int t0 = (int)f;
    t0 = min(t0, NTAB - 2);
    float w = f - (float)t0;
    int p = atomicAdd(&g_cnt[t], 1);
    g_perm[p] = (t0 << 16) | s;
    g_pw[p] = w;
}

__global__ void emb_kernel(const int* __restrict__ z, const float* __restrict__ emb) {
    int idx = blockIdx.x * blockDim.x + threadIdx.x;
    if (idx >= NN * HID) return;
    int n = idx >> 7, c = idx & 127;
    g_h[idx] = emb[z[n] * HID + c];
}

__global__ void cvec_kernel() {
    int t = blockIdx.x * blockDim.x + threadIdx.x;
    if (t >= NTAB) return;
    float dt = t * DELTA;
    g_C[t] = 0.5f * (cosf(dt * PI_O10) + 1.0f);
}

__global__ void tableH_kernel(const float* __restrict__ Wf1, const float* __restrict__ bf1) {
    int inter = blockIdx.y;
    int tbase = blockIdx.x * 8;
    __shared__ float W1s[NGAUSS * HID];
    __shared__ float eas[8][NGAUSS];
    const float* W1 = Wf1 + inter * NGAUSS * HID;
    for (int i = threadIdx.x; i < NGAUSS * HID; i += 128) W1s[i] = W1[i];
    for (int i = threadIdx.x; i < 8 * NGAUSS; i += 128) {
        int r = i / NGAUSS, k = i % NGAUSS;
        float dt = (tbase + r) * DELTA;
        float u = dt - k * GSPACE;
        eas[r][k] = expf(GCOEFF * u * u);
    }
    __syncthreads();
    float b = bf1[inter * HID + threadIdx.x];
#pragma unroll
    for (int r = 0; r < 8; r++) {
        float s = b;
#pragma unroll
        for (int k = 0; k < NGAUSS; k++) s += eas[r][k] * W1s[k * HID + threadIdx.x];
        g_H[(inter * NTAB + tbase + r) * HID + threadIdx.x] = sspf(s);
    }
}

// ---------------- MMA helpers ----------------
#define MMA16816(d, a, b0, b1) \
    asm volatile("mma.sync.aligned.m16n8k16.row.col.f32.bf16.bf16.f32 " \
        "{%0,%1,%2,%3}, {%4,%5,%6,%7}, {%8,%9}, {%0,%1,%2,%3};" \
        : "+f"((d)[0]), "+f"((d)[1]), "+f"((d)[2]), "+f"((d)[3]) \
        : "r"((a)[0]), "r"((a)[1]), "r"((a)[2]), "r"((a)[3]), "r"(b0), "r"(b1))

__device__ __forceinline__ void split2(float2 f, uint32_t& hi, uint32_t& lo) {
    __nv_bfloat162 h = __floats2bfloat162_rn(f.x, f.y);
    float lx = f.x - __bfloat162float(h.x);
    float ly = f.y - __bfloat162float(h.y);
    __nv_bfloat162 l = __floats2bfloat162_rn(lx, ly);
    hi = *(uint32_t*)&h;
    lo = *(uint32_t*)&l;
}

// ---------------- standalone GEMM (filter tables + first x), 2x1 warp tiling ----------------
#define MODE_PLAIN 0
#define MODE_FILT  3

template <int MODE>
__global__ __launch_bounds__(256) void gemm_mma(
    const float* __restrict__ A, const float* __restrict__ W,
    const float* __restrict__ bias, const float* __restrict__ extra,
    __nv_bfloat16* __restrict__ outB,
    size_t aStride, size_t wStride, size_t bStride, size_t oStride)
{
    __shared__ __nv_bfloat16 sBhi[128][72];
    __shared__ __nv_bfloat16 sBlo[128][72];

    A += (size_t)blockIdx.y * aStride;
    W += (size_t)blockIdx.y * wStride;
    if (bias) bias += (size_t)blockIdx.y * bStride;
    outB += (size_t)blockIdx.y * oStride;

    const int tid = threadIdx.x;
    const int w = tid >> 5, lane = tid & 31;
    const int wm = w >> 1, wn = w & 1;
    const int g = lane >> 2, tg = lane & 3;
    const int row0 = blockIdx.x * 128;

    float acc[2][8][4] = {};
    const float* aBase = A + (size_t)(row0 + wm * 32 + g) * 128;

    for (int kh = 0; kh < 2; kh++) {
        __syncthreads();
        for (int idx = tid; idx < 64 * 128; idx += 256) {
            int kp = idx >> 7, n = idx & 127;
            float v = W[(size_t)(kh * 64 + kp) * 128 + n];
            __nv_bfloat16 h = __float2bfloat16(v);
            sBhi[n][kp] = h;
            sBlo[n][kp] = __float2bfloat16(v - __bfloat162float(h));
        }
        __syncthreads();

#pragma unroll
        for (int ks = 0; ks < 4; ks++) {
            int kc = kh * 64 + ks * 16 + tg * 2;
            uint32_t ahi[2][4], alo[2][4];
#pragma unroll
            for (int mt = 0; mt < 2; mt++) {
                const float* rp = aBase + (size_t)mt * 16 * 128;
                split2(*(const float2*)(rp + kc),            ahi[mt][0], alo[mt][0]);
                split2(*(const float2*)(rp + 8 * 128 + kc),  ahi[mt][1], alo[mt][1]);
                split2(*(const float2*)(rp + kc + 8),        ahi[mt][2], alo[mt][2]);
                split2(*(const float2*)(rp + 8 * 128 + kc + 8), ahi[mt][3], alo[mt][3]);
            }
            int c = ks * 16 + tg * 2;
#pragma unroll
            for (int nt = 0; nt < 8; nt++) {
                int n = wn * 64 + nt * 8 + g;
                uint32_t bh0 = *(const uint32_t*)&sBhi[n][c];
                uint32_t bh1 = *(const uint32_t*)&sBhi[n][c + 8];
                uint32_t bl0 = *(const uint32_t*)&sBlo[n][c];
                uint32_t bl1 = *(const uint32_t*)&sBlo[n][c + 8];
#pragma unroll
                for (int mt = 0; mt < 2; mt++) {
                    MMA16816(acc[mt][nt], ahi[mt], bh0, bh1);
                    MMA16816(acc[mt][nt], ahi[mt], bl0, bl1);
                    MMA16816(acc[mt][nt], alo[mt], bh0, bh1);
                }
            }
        }
    }

#pragma unroll
    for (int mt = 0; mt < 2; mt++) {
        int r0 = row0 + wm * 32 + mt * 16 + g;
        int r1 = r0 + 8;
        float s0 = 1.0f, s1 = 1.0f;
        if (MODE == MODE_FILT) { s0 = extra[r0]; s1 = extra[r1]; }
#pragma unroll
        for (int nt = 0; nt < 8; nt++) {
            int cc = wn * 64 + nt * 8 + tg * 2;
            float vx0 = acc[mt][nt][0], vy0 = acc[mt][nt][1];
            float vx1 = acc[mt][nt][2], vy1 = acc[mt][nt][3];
            if (MODE == MODE_FILT) {
                float2 bv = *(const float2*)(bias + cc);
                vx0 = (vx0 + bv.x) * s0; vy0 = (vy0 + bv.y) * s0;
                vx1 = (vx1 + bv.x) * s1; vy1 = (vy1 + bv.y) * s1;
            }
            *(__nv_bfloat162*)(outB + (size_t)r0 * 128 + cc) = __floats2bfloat162_rn(vx0, vy0);
            *(__nv_bfloat162*)(outB + (size_t)r1 * 128 + cc) = __floats2bfloat162_rn(vx1, vy1);
        }
    }
}

// ---------------- fused interaction-update kernel ----------------
// Chains in registers (16 rows/warp, full K per warp):
//   t  = ssp(agg @ Wl2 + bl2)
//   hn = t @ Wl + bl + h        -> written to h
//   LAST=0: x = hn @ W3 (=Wl1_next)  -> bf16 xb
//   LAST=1: v = ssp(hn @ W3 (=Wo1) + bo1) . Wo2 -> atomicAdd(g_sum)
template <bool LAST>
__global__ __launch_bounds__(256) void update_kernel(
    const float* __restrict__ agg, float* __restrict__ h,
    const float* __restrict__ Wl2, const float* __restrict__ bl2,
    const float* __restrict__ Wl, const float* __restrict__ bl,
    const float* __restrict__ W3,
    const float* __restrict__ bo1, const float* __restrict__ Wo2,
    __nv_bfloat16* __restrict__ xb)
{
    __shared__ __nv_bfloat16 sBhi[128][72];
    __shared__ __nv_bfloat16 sBlo[128][72];
    const int tid = threadIdx.x, w = tid >> 5, lane = tid & 31;
    const int g = lane >> 2, tg = lane & 3;
    const int rg = blockIdx.x * 128 + w * 16 + g;   // rows rg, rg+8

    // ======== GEMM1: t = ssp(agg @ Wl2 + bl2) ========
    float acc[16][4] = {};
    {
        const float* r0p = agg + (size_t)rg * 128;
        const float* r1p = r0p + 8 * 128;
        for (int kh = 0; kh < 2; kh++) {
            __syncthreads();
            for (int idx = tid; idx < 64 * 128; idx += 256) {
                int kp = idx >> 7, n = idx & 127;
                float v = Wl2[(size_t)(kh * 64 + kp) * 128 + n];
                __nv_bfloat16 hh = __float2bfloat16(v);
                sBhi[n][kp] = hh;
                sBlo[n][kp] = __float2bfloat16(v - __bfloat162float(hh));
            }
            __syncthreads();
#pragma unroll
            for (int ks = 0; ks < 4; ks++) {
                int kc = kh * 64 + ks * 16 + tg * 2;
                uint32_t ahi[4], alo[4];
                split2(*(const float2*)(r0p + kc),     ahi[0], alo[0]);
                split2(*(const float2*)(r1p + kc),     ahi[1], alo[1]);
                split2(*(const float2*)(r0p + kc + 8), ahi[2], alo[2]);
                split2(*(const float2*)(r1p + kc + 8), ahi[3], alo[3]);
                int c = ks * 16 + tg * 2;
#pragma unroll
                for (int nt = 0; nt < 16; nt++) {
                    int n = nt * 8 + g;
                    uint32_t bh0 = *(const uint32_t*)&sBhi[n][c];
                    uint32_t bh1 = *(const uint32_t*)&sBhi[n][c + 8];
                    uint32_t bl0 = *(const uint32_t*)&sBlo[n][c];
                    uint32_t bl1 = *(const uint32_t*)&sBlo[n][c + 8];
                    MMA16816(acc[nt], ahi, bh0, bh1);
                    MMA16816(acc[nt], ahi, bl0, bl1);
                    MMA16816(acc[nt], alo, bh0, bh1);
                }
            }
        }
#pragma unroll
        for (int nt = 0; nt < 16; nt++) {
            float2 bv = *(const float2*)(bl2 + nt * 8 + tg * 2);
            acc[nt][0] = sspf(acc[nt][0] + bv.x);
            acc[nt][1] = sspf(acc[nt][1] + bv.y);
            acc[nt][2] = sspf(acc[nt][2] + bv.x);
            acc[nt][3] = sspf(acc[nt][3] + bv.y);
        }
    }

    // ======== GEMM2: hn = t @ Wl + bl + h ========
    float acc2[16][4] = {};
    for (int kh = 0; kh < 2; kh++) {
        __syncthreads();
        for (int idx = tid; idx < 64 * 128; idx += 256) {
            int kp = idx >> 7, n = idx & 127;
            float v = Wl[(size_t)(kh * 64 + kp) * 128 + n];
            __nv_bfloat16 hh = __float2bfloat16(v);
            sBhi[n][kp] = hh;
            sBlo[n][kp] = __float2bfloat16(v - __bfloat162float(hh));
        }
        __syncthreads();
#pragma unroll
        for (int ks = 0; ks < 4; ks++) {
            int j = kh * 4 + ks;
            uint32_t ahi[4], alo[4];
            split2(make_float2(acc[2 * j][0],     acc[2 * j][1]),     ahi[0], alo[0]);
            split2(make_float2(acc[2 * j][2],     acc[2 * j][3]),     ahi[1], alo[1]);
            split2(make_float2(acc[2 * j + 1][0], acc[2 * j + 1][1]), ahi[2], alo[2]);
            split2(make_float2(acc[2 * j + 1][2], acc[2 * j + 1][3]), ahi[3], alo[3]);
            int c = ks * 16 + tg * 2;
#pragma unroll
            for (int nt = 0; nt < 16; nt++) {
                int n = nt * 8 + g;
                uint32_t bh0 = *(const uint32_t*)&sBhi[n][c];
                uint32_t bh1 = *(const uint32_t*)&sBhi[n][c + 8];
                uint32_t bl0 = *(const uint32_t*)&sBlo[n][c];
                uint32_t bl1 = *(const uint32_t*)&sBlo[n][c + 8];
                MMA16816(acc2[nt], ahi, bh0, bh1);
                MMA16816(acc2[nt], ahi, bl0, bl1);
                MMA16816(acc2[nt], alo, bh0, bh1);
            }
        }
    }
    {
        float* h0p = h + (size_t)rg * 128;
        float* h1p = h0p + 8 * 128;
#pragma unroll
        for (int nt = 0; nt < 16; nt++) {
            int cc = nt * 8 + tg * 2;
            float2 bv = *(const float2*)(bl + cc);
            float2 e0 = *(const float2*)(h0p + cc);
            float2 e1 = *(const float2*)(h1p + cc);
            acc2[nt][0] += bv.x + e0.x; acc2[nt][1] += bv.y + e0.y;
            acc2[nt][2] += bv.x + e1.x; acc2[nt][3] += bv.y + e1.y;
            *(float2*)(h0p + cc) = make_float2(acc2[nt][0], acc2[nt][1]);
            *(float2*)(h1p + cc) = make_float2(acc2[nt][2], acc2[nt][3]);
        }
    }

    // ======== GEMM3: x_next or readout ========
    constexpr int NT3 = LAST ? 8 : 16;
    constexpr int NC3 = LAST ? 64 : 128;
    float acc3[NT3][4] = {};
    for (int kh = 0; kh < 2; kh++) {
        __syncthreads();
        for (int idx = tid; idx < 64 * NC3; idx += 256) {
            int kp = idx / NC3, n = idx % NC3;
            float v = W3[(size_t)(kh * 64 + kp) * NC3 + n];
            __nv_bfloat16 hh = __float2bfloat16(v);
            sBhi[n][kp] = hh;
            sBlo[n][kp] = __float2bfloat16(v - __bfloat162float(hh));
        }
        __syncthreads();
#pragma unroll
        for (int ks = 0; ks < 4; ks++) {
            int j = kh * 4 + ks;
            uint32_t ahi[4], alo[4];
            split2(make_float2(acc2[2 * j][0],     acc2[2 * j][1]),     ahi[0], alo[0]);
            split2(make_float2(acc2[2 * j][2],     acc2[2 * j][3]),     ahi[1], alo[1]);
            split2(make_float2(acc2[2 * j + 1][0], acc2[2 * j + 1][1]), ahi[2], alo[2]);
            split2(make_float2(acc2[2 * j + 1][2], acc2[2 * j + 1][3]), ahi[3], alo[3]);
            int c = ks * 16 + tg * 2;
#pragma unroll
            for (int nt = 0; nt < NT3; nt++) {
                int n = nt * 8 + g;
                uint32_t bh0 = *(const uint32_t*)&sBhi[n][c];
                uint32_t bh1 = *(const uint32_t*)&sBhi[n][c + 8];
                uint32_t bl0 = *(const uint32_t*)&sBlo[n][c];
                uint32_t bl1 = *(const uint32_t*)&sBlo[n][c + 8];
                MMA16816(acc3[nt], ahi, bh0, bh1);
                MMA16816(acc3[nt], ahi, bl0, bl1);
                MMA16816(acc3[nt], alo, bh0, bh1);
            }
        }
    }
    if (!LAST) {
        __nv_bfloat16* x0p = xb + (size_t)rg * 128;
        __nv_bfloat16* x1p = x0p + 8 * 128;
#pragma unroll
        for (int nt = 0; nt < 16; nt++) {
            int cc = nt * 8 + tg * 2;
            *(__nv_bfloat162*)(x0p + cc) = __floats2bfloat162_rn(acc3[nt][0], acc3[nt][1]);
            *(__nv_bfloat162*)(x1p + cc) = __floats2bfloat162_rn(acc3[nt][2], acc3[nt][3]);
        }
    } else {
        float v = 0.0f;
#pragma unroll
        for (int nt = 0; nt < 8; nt++) {
            int cc = nt * 8 + tg * 2;
            float2 bo = *(const float2*)(bo1 + cc);
            float2 w2 = *(const float2*)(Wo2 + cc);
            v += sspf(acc3[nt][0] + bo.x) * w2.x + sspf(acc3[nt][1] + bo.y) * w2.y;
            v += sspf(acc3[nt][2] + bo.x) * w2.x + sspf(acc3[nt][3] + bo.y) * w2.y;
        }
#pragma unroll
        for (int off = 16; off > 0; off >>= 1)
            v += __shfl_xor_sync(0xFFFFFFFFu, v, off);
        if (lane == 0) atomicAdd(&g_sum, v);
    }
}

// ---------------- edge aggregation (dst-sorted, warp per node, 2x unrolled) ----------------
__device__ __forceinline__ float4 edge_term(const __nv_bfloat16* xb, const __nv_bfloat16* Tb,
                                            int pk, float wt, int lane) {
    int s = pk & 0xFFFF;
    int t0 = pk >> 16;
    uint2 xv = ((const uint2*)(xb + (size_t)s * 128))[lane];
    uint2 a0 = ((const uint2*)(Tb + (size_t)t0 * 128))[lane];
    uint2 a1 = ((const uint2*)(Tb + (size_t)(t0 + 1) * 128))[lane];
    float2 x0 = __bfloat1622float2(*(__nv_bfloat162*)&xv.x);
    float2 x1 = __bfloat1622float2(*(__nv_bfloat162*)&xv.y);
    float2 p0 = __bfloat1622float2(*(__nv_bfloat162*)&a0.x);
    float2 p1 = __bfloat1622float2(*(__nv_bfloat162*)&a0.y);
    float2 q0 = __bfloat1622float2(*(__nv_bfloat162*)&a1.x);
    float2 q1 = __bfloat1622float2(*(__nv_bfloat162*)&a1.y);
    float w0 = 1.0f - wt;
    float4 r;
    r.x = x0.x * (w0 * p0.x + wt * q0.x);
    r.y = x0.y * (w0 * p0.y + wt * q0.y);
    r.z = x1.x * (w0 * p1.x + wt * q1.x);
    r.w = x1.y * (w0 * p1.y + wt * q1.y);
    return r;
}

__global__ void agg_kernel(const __nv_bfloat16* __restrict__ xb,
                           const __nv_bfloat16* __restrict__ Tb) {
    int warp = (blockIdx.x * blockDim.x + threadIdx.x) >> 5;
    int lane = threadIdx.x & 31;
    if (warp >= NN) return;
    int b = g_start[warp];
    int e = g_start[warp + 1];
    float4 acc = make_float4(0.f, 0.f, 0.f, 0.f);
    int j = b;
    for (; j + 2 <= e; j += 2) {
        int pk0 = g_perm[j], pk1 = g_perm[j + 1];
        float w0 = g_pw[j], w1 = g_pw[j + 1];
        float4 r0 = edge_term(xb, Tb, pk0, w0, lane);
        float4 r1 = edge_term(xb, Tb, pk1, w1, lane);
        acc.x += r0.x + r1.x;
        acc.y += r0.y + r1.y;
        acc.z += r0.z + r1.z;
        acc.w += r0.w + r1.w;
    }
    if (j < e) {
        float4 r0 = edge_term(xb, Tb, g_perm[j], g_pw[j], lane);
        acc.x += r0.x; acc.y += r0.y; acc.z += r0.z; acc.w += r0.w;
    }
    ((float4*)(g_agg + (size_t)warp * 128))[lane] = acc;
}

__global__ void final_kernel(float* __restrict__ out, const float* __restrict__ bo2) {
    float v = g_sum + (float)NN * bo2[0];
    out[0] = fmaxf(v, 0.0f);
}

// ---------------- launch ----------------
extern "C" void kernel_launch(void* const* d_in, const int* in_sizes, int n_in,
                              void* d_out, int out_size) {
    const int*   z    = (const int*)d_in[0];
    const float* pos  = (const float*)d_in[1];
    const int*   ei   = (const int*)d_in[2];
    const float* emb  = (const float*)d_in[3];
    const float* Wf1  = (const float*)d_in[4];
    const float* bf1  = (const float*)d_in[5];
    const float* Wf2  = (const float*)d_in[6];
    const float* bf2  = (const float*)d_in[7];
    const float* Wl1  = (const float*)d_in[8];
    const float* Wl2  = (const float*)d_in[9];
    const float* bl2  = (const float*)d_in[10];
    const float* Wl   = (const float*)d_in[11];
    const float* bl   = (const float*)d_in[12];
    const float* Wo1  = (const float*)d_in[13];
    const float* bo1  = (const float*)d_in[14];
    const float* Wo2  = (const float*)d_in[15];
    const float* bo2  = (const float*)d_in[16];
    float* out = (float*)d_out;

    float *p_h, *p_agg, *p_H, *p_C;
    __nv_bfloat16 *p_xb, *p_Tb;
    cudaGetSymbolAddress((void**)&p_h,   g_h);
    cudaGetSymbolAddress((void**)&p_agg, g_agg);
    cudaGetSymbolAddress((void**)&p_H,   g_H);
    cudaGetSymbolAddress((void**)&p_C,   g_C);
    cudaGetSymbolAddress((void**)&p_xb,  g_xb);
    cudaGetSymbolAddress((void**)&p_Tb,  g_Tb);

    // --- edge prep + dst sort ---
    zero_kernel<<<NN / 256, 256>>>();
    prep_kernel<<<EE / 256, 256>>>(pos, ei);
    scan_kernel<<<1, 1024>>>();
    scatter_kernel<<<EE / 256, 256>>>(ei);
    emb_kernel<<<NN * HID / 256, 256>>>(z, emb);

    // --- filter tables (batched over all 6 interactions) ---
    cvec_kernel<<<NTAB / 256, 256>>>();
    tableH_kernel<<<dim3(NTAB / 8, NINTER), 128>>>(Wf1, bf1);
    gemm_mma<MODE_FILT><<<dim3(NTAB / 128, NINTER), 256>>>(
        p_H, Wf2, bf2, p_C, p_Tb,
        (size_t)NTAB * HID, (size_t)HID * HID, (size_t)HID, (size_t)NTAB * HID);

    // --- first x = h @ Wl1[0] ---
    gemm_mma<MODE_PLAIN><<<NN / 128, 256>>>(
        p_h, Wl1, nullptr, nullptr, p_xb, 0, 0, 0, 0);

    // --- interaction blocks: agg + fused node update ---
    for (int i = 0; i < NINTER; i++) {
        agg_kernel<<<NN / 8, 256>>>(p_xb, p_Tb + (size_t)i * NTAB * HID);
        if (i < NINTER - 1) {
            update_kernel<false><<<NN / 128, 256>>>(
                p_agg, p_h,
                Wl2 + (size_t)i * HID * HID, bl2 + (size_t)i * HID,
                Wl  + (size_t)i * HID * HID, bl  + (size_t)i * HID,
                Wl1 + (size_t)(i + 1) * HID * HID, nullptr, nullptr, p_xb);
        } else {
            update_kernel<true><<<NN / 128, 256>>>(
                p_agg, p_h,
                Wl2 + (size_t)i * HID * HID, bl2 + (size_t)i * HID,
                Wl  + (size_t)i * HID * HID, bl  + (size_t)i * HID,
                Wo1, bo1, Wo2, nullptr);
        }
    }

    final_kernel<<<1, 1>>>(out, bo2);
}